// round 8
// baseline (speedup 1.0000x reference)
#include <cuda_runtime.h>
#include <cstdint>

#define BATCH 4
#define CH    64
#define H     256
#define WID   256
#define HW    (H*WID)
#define CHW   (CH*HW)
#define XT    64            // x-tile per block
#define C2ROWS 257          // center rows -1..255 stored at index yc+1

// scratch (allocation-free: __device__ globals)
__device__ float  g_s[BATCH*HW];                   // per-pixel vertical shift s
__device__ float  g_x2[BATCH*CHW];                 // warped image
__device__ float  g_up[BATCH*CHW];                 // upper conv result
__device__ float  g_C2[BATCH*CH*C2ROWS*WID];       // conv3x3(x2) at rows -1..255
__device__ float2 g_Wd[CH*9*CH];                   // [c][tap][oc] duplicated (w,w)

// packed fp32x2 FMA (Blackwell FFMA2 — only reachable via PTX)
#define FMA2(d,a,b) asm("fma.rn.f32x2 %0, %1, %2, %3;" : "=l"(d) : "l"(a), "l"(b), "l"(d))

__device__ __forceinline__ float lo32(uint64_t v){ return __uint_as_float((unsigned)(v & 0xffffffffu)); }
__device__ __forceinline__ float hi32(uint64_t v){ return __uint_as_float((unsigned)(v >> 32)); }

// ---------------------------------------------------------------------------
// Kernel W: transpose+duplicate weights [oc][c][tap] -> [c][tap][oc] as (w,w)
// ---------------------------------------------------------------------------
__global__ __launch_bounds__(256) void wt_kernel(const float* __restrict__ Wg) {
    int i = blockIdx.x * 256 + threadIdx.x;
    if (i >= CH*CH*9) return;
    int oc  = i / (CH*9);
    int rem = i - oc*CH*9;
    int c   = rem / 9;
    int tap = rem - c*9;
    float w = Wg[i];
    g_Wd[(c*9 + tap)*CH + oc] = make_float2(w, w);
}

// ---------------------------------------------------------------------------
// Kernel A: per-pixel channel max -> depth -> s, and vertical bilinear warp x2
// ---------------------------------------------------------------------------
__global__ __launch_bounds__(256) void prep_kernel(const float* __restrict__ X) {
    int idx = blockIdx.x * 256 + threadIdx.x;
    if (idx >= BATCH*HW) return;
    int b   = idx / HW;
    int rem = idx - b*HW;
    int y   = rem / WID;
    int x   = rem - y*WID;

    const float* Xpix = X + b*CHW + y*WID + x;
    float m = -1e30f;
    #pragma unroll 8
    for (int c = 0; c < CH; c++) m = fmaxf(m, Xpix[c*HW]);

    float depth = fminf(fmaxf(m, 1.0f), 50.0f);
    float s = 50.0f / (2.0f * depth);          // FOCAL/(downsample*depth)
    g_s[idx] = s;

    float ys = (float)y - s;
    float fy = floorf(ys);
    int   y0 = (int)fy;
    float w1 = ys - fy;
    float w0 = 1.0f - w1;

    bool ok0 = (y0   >= 0) && (y0   < H);
    bool ok1 = (y0+1 >= 0) && (y0+1 < H);
    const float* Xc0 = X + b*CHW + (ok0 ? y0   : 0)*WID + x;
    const float* Xc1 = X + b*CHW + (ok1 ? y0+1 : 0)*WID + x;
    float* X2p = g_x2 + b*CHW + y*WID + x;

    #pragma unroll 4
    for (int c = 0; c < CH; c++) {
        float a  = ok0 ? Xc0[c*HW] : 0.0f;
        float bb = ok1 ? Xc1[c*HW] : 0.0f;
        X2p[c*HW] = w0*a + w1*bb;
    }
}

// ---------------------------------------------------------------------------
// Paired FFMA2 3x3 conv: lane pair = (X, x2) at the SAME (row,col).
// lo lane accumulates upper = conv(X), hi lane accumulates C2 = conv(x2).
// Block: 64 oc x 64 px, 256 threads, per-thread 4 oc x 4 px (16 f32x2 accs).
// Center row yy = blockIdx.y - 1 in [-1, 255]; upper stored only for yy>=0,
// C2 stored at row index yy+1.
// ---------------------------------------------------------------------------
__global__ __launch_bounds__(256, 2) void conv_pair_kernel(const float* __restrict__ X) {
    __shared__ __align__(16) float2 sW[2][9*CH];     // duplicated weight pairs
    __shared__ __align__(16) float2 sP[2][3][66];    // (X, x2) pair rows

    const int x0 = blockIdx.x * XT;
    const int yy = (int)blockIdx.y - 1;              // center row
    const int b  = blockIdx.z;
    const int t  = threadIdx.x;

    const int ocb = (t & 15) * 4;      // out-channel base
    const int pxb = (t >> 4) * 4;      // pixel base within tile

    uint64_t acc[4][4];
    #pragma unroll
    for (int o = 0; o < 4; o++)
        #pragma unroll
        for (int p = 0; p < 4; p++) acc[o][p] = 0ull;

    const float* Xb = X    + b*CHW;
    const float* Zb = g_x2 + b*CHW;

    auto stage = [&](int buf, int c) {
        const float2* Wc = g_Wd + c*9*CH;
        #pragma unroll
        for (int i = t; i < 9*CH; i += 256) sW[buf][i] = Wc[i];
        const float* Xc = Xb + c*HW;
        const float* Zc = Zb + c*HW;
        for (int i = t; i < 3*66; i += 256) {
            int r = i / 66, j = i - r*66;
            int row = yy - 1 + r, col = x0 - 1 + j;
            float a = 0.0f, v = 0.0f;
            if (row >= 0 && row < H && col >= 0 && col < WID) {
                int off = row*WID + col;
                a = __ldg(Xc + off);
                v = __ldg(Zc + off);
            }
            sP[buf][r][j] = make_float2(a, v);
        }
    };

    stage(0, 0);
    __syncthreads();
    int buf = 0;

    for (int c = 0; c < CH; c++) {
        if (c + 1 < CH) stage(buf ^ 1, c + 1);

        #pragma unroll
        for (int ky = 0; ky < 3; ky++) {
            uint64_t rj[6];
            const ulonglong2* rp = (const ulonglong2*)&sP[buf][ky][pxb];
            #pragma unroll
            for (int j = 0; j < 3; j++) {
                ulonglong2 q = rp[j];
                rj[2*j]   = q.x;
                rj[2*j+1] = q.y;
            }
            #pragma unroll
            for (int kx = 0; kx < 3; kx++) {
                const ulonglong2* wp = (const ulonglong2*)&sW[buf][(ky*3+kx)*CH + ocb];
                ulonglong2 wq0 = wp[0];
                ulonglong2 wq1 = wp[1];
                uint64_t w[4] = {wq0.x, wq0.y, wq1.x, wq1.y};
                #pragma unroll
                for (int o = 0; o < 4; o++) {
                    #pragma unroll
                    for (int p = 0; p < 4; p++) FMA2(acc[o][p], w[o], rj[p + kx]);
                }
            }
        }
        __syncthreads();
        buf ^= 1;
    }

    const int x = x0 + pxb;
    const int c2row = yy + 1;                        // 0..256, always valid

    #pragma unroll
    for (int o = 0; o < 4; o++) {
        int oc = ocb + o;
        float4 hv = make_float4(hi32(acc[o][0]), hi32(acc[o][1]), hi32(acc[o][2]), hi32(acc[o][3]));
        *(float4*)(g_C2 + ((long)(b*CH + oc)*C2ROWS + c2row)*WID + x) = hv;
        if (yy >= 0) {
            float4 lv = make_float4(lo32(acc[o][0]), lo32(acc[o][1]), lo32(acc[o][2]), lo32(acc[o][3]));
            *(float4*)(g_up + ((long)(b*CH + oc)*H + yy)*WID + x) = lv;
        }
    }
}

// ---------------------------------------------------------------------------
// Combine: out = min(upper, w0*C2[y0] + w1*C2[y0+1]) — memory-bound epilogue.
// Thread = (b, y, 4-px group); loops all 64 oc reusing the interp params.
// ---------------------------------------------------------------------------
__global__ __launch_bounds__(256) void combine_kernel(float* __restrict__ Out) {
    int idx = blockIdx.x * 256 + threadIdx.x;
    const int NPX = BATCH * H * (WID/4);
    if (idx >= NPX) return;
    int b   = idx / (H * (WID/4));
    int rem = idx - b * (H * (WID/4));
    int y   = rem / (WID/4);
    int x   = (rem - y * (WID/4)) * 4;

    int   y0i[4];
    float w0f[4], w1f[4];
    #pragma unroll
    for (int p = 0; p < 4; p++) {
        float s  = g_s[b*HW + y*WID + x + p];
        float ys = (float)y - s;
        float fy = floorf(ys);
        y0i[p] = (int)fy;
        w1f[p] = ys - fy;
        w0f[p] = 1.0f - w1f[p];
    }

    const float* upb = g_up + (long)b*CHW + y*WID + x;
    const float* c2b = g_C2 + (long)b*CH*C2ROWS*WID + x;
    float* ob = Out + (long)b*CHW + y*WID + x;

    for (int oc = 0; oc < CH; oc++) {
        float4 u = *(const float4*)(upb + (long)oc*HW);
        const float* cc = c2b + (long)oc*C2ROWS*WID;
        float r[4];
        #pragma unroll
        for (int p = 0; p < 4; p++) {
            int y0 = y0i[p];
            float A = (y0 >= -1) ? cc[(y0+1)*WID + p] : 0.0f;
            float B = (y0 >= -2) ? cc[(y0+2)*WID + p] : 0.0f;
            r[p] = w0f[p]*A + w1f[p]*B;
        }
        float4 res = make_float4(fminf(u.x, r[0]), fminf(u.y, r[1]),
                                 fminf(u.z, r[2]), fminf(u.w, r[3]));
        *(float4*)(ob + (long)oc*HW) = res;
    }
}

// ---------------------------------------------------------------------------
extern "C" void kernel_launch(void* const* d_in, const int* in_sizes, int n_in,
                              void* d_out, int out_size) {
    const float* X  = (const float*)d_in[0];   // [4,64,256,256]
    const float* Wg = (const float*)d_in[1];   // [64,64,3,3]
    float* Out = (float*)d_out;                // [4,64,256,256]

    wt_kernel<<<(CH*CH*9 + 255)/256, 256>>>(Wg);
    prep_kernel<<<(BATCH*HW + 255)/256, 256>>>(X);

    // fused dual conv: upper = conv(X), C2 = conv(x2), center rows -1..255
    {
        dim3 grid(WID/XT, C2ROWS, BATCH);
        conv_pair_kernel<<<grid, 256>>>(X);
    }
    // interp + min epilogue
    {
        int npx = BATCH * H * (WID/4);
        combine_kernel<<<(npx + 255)/256, 256>>>(Out);
    }
}

// round 10
// speedup vs baseline: 2.5419x; 2.5419x over previous
#include <cuda_runtime.h>
#include <cuda_bf16.h>
#include <cstdint>

#define BATCH 4
#define CH    64
#define H     256
#define WID   256
#define HW    (H*WID)
#define CHW   (CH*HW)
#define C2ROWS 257          // center rows -1..255 stored at index yc+1
#define NPX   32            // pixels per block (N tile)

// scratch (allocation-free: __device__ globals)
__device__ float g_s[BATCH*HW];                    // per-pixel vertical shift s
__device__ float g_x2[BATCH*CHW];                  // warped image
__device__ float g_up[BATCH*CHW];                  // upper conv result
__device__ float g_C2[BATCH*CH*C2ROWS*WID];        // conv3x3(x2) at rows -1..255
__device__ __nv_bfloat16 g_Wh[4*9*64*16];          // weight hi: [cc][tap][oc][c']
__device__ __nv_bfloat16 g_Wl[4*9*64*16];          // weight lo

// ---------------------------------------------------------------------------
// mma.sync m16n8k16 bf16, fp32 accumulate
// ---------------------------------------------------------------------------
__device__ __forceinline__ void mma16816(float* d, const uint32_t* a, uint32_t b0, uint32_t b1) {
    asm volatile(
        "mma.sync.aligned.m16n8k16.row.col.f32.bf16.bf16.f32 "
        "{%0,%1,%2,%3}, {%4,%5,%6,%7}, {%8,%9}, {%0,%1,%2,%3};\n"
        : "+f"(d[0]), "+f"(d[1]), "+f"(d[2]), "+f"(d[3])
        : "r"(a[0]), "r"(a[1]), "r"(a[2]), "r"(a[3]), "r"(b0), "r"(b1));
}

// ---------------------------------------------------------------------------
// Kernel W: split weights into bf16 hi/lo, layout [cc=c/16][tap][oc][c%16]
// ---------------------------------------------------------------------------
__global__ __launch_bounds__(256) void wt_kernel(const float* __restrict__ Wg) {
    int i = blockIdx.x * 256 + threadIdx.x;
    if (i >= CH*CH*9) return;
    int oc  = i / (CH*9);
    int rem = i - oc*CH*9;
    int c   = rem / 9;
    int tap = rem - c*9;
    float w = Wg[i];
    __nv_bfloat16 h = __float2bfloat16(w);
    __nv_bfloat16 l = __float2bfloat16(w - __bfloat162float(h));
    int cc = c >> 4, cp = c & 15;
    int dst = ((cc*9 + tap)*64 + oc)*16 + cp;
    g_Wh[dst] = h;
    g_Wl[dst] = l;
}

// ---------------------------------------------------------------------------
// Kernel A: per-pixel channel max -> depth -> s, and vertical bilinear warp x2
// ---------------------------------------------------------------------------
__global__ __launch_bounds__(256) void prep_kernel(const float* __restrict__ X) {
    int idx = blockIdx.x * 256 + threadIdx.x;
    if (idx >= BATCH*HW) return;
    int b   = idx / HW;
    int rem = idx - b*HW;
    int y   = rem / WID;
    int x   = rem - y*WID;

    const float* Xpix = X + b*CHW + y*WID + x;
    float m = -1e30f;
    #pragma unroll 8
    for (int c = 0; c < CH; c++) m = fmaxf(m, Xpix[c*HW]);

    float depth = fminf(fmaxf(m, 1.0f), 50.0f);
    float s = 50.0f / (2.0f * depth);          // FOCAL/(downsample*depth)
    g_s[idx] = s;

    float ys = (float)y - s;
    float fy = floorf(ys);
    int   y0 = (int)fy;
    float w1 = ys - fy;
    float w0 = 1.0f - w1;

    bool ok0 = (y0   >= 0) && (y0   < H);
    bool ok1 = (y0+1 >= 0) && (y0+1 < H);
    const float* Xc0 = X + b*CHW + (ok0 ? y0   : 0)*WID + x;
    const float* Xc1 = X + b*CHW + (ok1 ? y0+1 : 0)*WID + x;
    float* X2p = g_x2 + b*CHW + y*WID + x;

    #pragma unroll 4
    for (int c = 0; c < CH; c++) {
        float a  = ok0 ? Xc0[c*HW] : 0.0f;
        float bb = ok1 ? Xc1[c*HW] : 0.0f;
        X2p[c*HW] = w0*a + w1*bb;
    }
}

// ---------------------------------------------------------------------------
// Tensor-core conv: block = 64 oc x 32 px for one (b, center-row).
// 128 threads = 4 warps; warp w computes oc rows [16w,16w+16) x all 32 px.
// K loop: 4 chunks of 16 channels; per chunk, 9 taps; per tap 3 split mmas
// per n8 fragment (hh, hl, lh).
// MODE 0: in = X, store g_up at row yc (yc in [0,255]).
// MODE 1: in = g_x2, store g_C2 at row index yc+1 (yc in [-1,255]).
// ---------------------------------------------------------------------------
template<int MODE>
__global__ __launch_bounds__(128) void conv_mma_kernel(const float* __restrict__ in) {
    __shared__ __align__(16) __nv_bfloat16 sBh[2][3][34][18];
    __shared__ __align__(16) __nv_bfloat16 sBl[2][3][34][18];

    const int t    = threadIdx.x;
    const int w    = t >> 5;
    const int lane = t & 31;
    const int g    = lane >> 2;
    const int tig  = lane & 3;

    const int x0 = blockIdx.x * NPX;
    const int yc = MODE ? ((int)blockIdx.y - 1) : (int)blockIdx.y;
    const int b  = blockIdx.z;

    float acc[4][4];
    #pragma unroll
    for (int nf = 0; nf < 4; nf++)
        #pragma unroll
        for (int k = 0; k < 4; k++) acc[nf][k] = 0.0f;

    // ---- stage one 16-channel chunk of 3 input rows (hi/lo bf16) ----
    auto stage = [&](int buf, int cc) {
        const float* inb = in + ((long)b*CH + cc*16)*HW;
        for (int i = t; i < 16*3*34; i += 128) {
            int cp  = i / 102;
            int rem = i - cp*102;
            int r   = rem / 34;
            int px  = rem - r*34;
            int row = yc + r - 1;
            int col = x0 + px - 1;
            float v = 0.0f;
            if (row >= 0 && row < H && col >= 0 && col < WID)
                v = __ldg(inb + (long)cp*HW + row*WID + col);
            __nv_bfloat16 h = __float2bfloat16(v);
            __nv_bfloat16 l = __float2bfloat16(v - __bfloat162float(h));
            sBh[buf][r][px][cp] = h;
            sBl[buf][r][px][cp] = l;
        }
    };

    stage(0, 0);
    __syncthreads();
    int buf = 0;

    const uint32_t* AW_h = (const uint32_t*)g_Wh;
    const uint32_t* AW_l = (const uint32_t*)g_Wl;

    for (int cc = 0; cc < 4; cc++) {
        if (cc < 3) stage(buf ^ 1, cc + 1);

        #pragma unroll
        for (int tap = 0; tap < 9; tap++) {
            const int ky = tap / 3;
            const int kx = tap - ky*3;

            // A fragments (weights) from global (L1-resident after first use)
            const int abase = ((cc*9 + tap)*64 + w*16 + g)*8 + tig;
            uint32_t ah[4], al[4];
            ah[0] = __ldg(AW_h + abase);
            ah[1] = __ldg(AW_h + abase + 64);
            ah[2] = __ldg(AW_h + abase + 4);
            ah[3] = __ldg(AW_h + abase + 68);
            al[0] = __ldg(AW_l + abase);
            al[1] = __ldg(AW_l + abase + 64);
            al[2] = __ldg(AW_l + abase + 4);
            al[3] = __ldg(AW_l + abase + 68);

            #pragma unroll
            for (int nf = 0; nf < 4; nf++) {
                const int pxi = nf*8 + g + kx;
                uint32_t bh0 = *(const uint32_t*)&sBh[buf][ky][pxi][tig*2];
                uint32_t bh1 = *(const uint32_t*)&sBh[buf][ky][pxi][tig*2 + 8];
                uint32_t bl0 = *(const uint32_t*)&sBl[buf][ky][pxi][tig*2];
                uint32_t bl1 = *(const uint32_t*)&sBl[buf][ky][pxi][tig*2 + 8];
                mma16816(acc[nf], ah, bh0, bh1);   // hi*hi
                mma16816(acc[nf], ah, bl0, bl1);   // hi*lo
                mma16816(acc[nf], al, bh0, bh1);   // lo*hi
            }
        }
        __syncthreads();
        buf ^= 1;
    }

    // ---- epilogue: write D[oc, px] ----
    const int ocb = w*16;
    #pragma unroll
    for (int nf = 0; nf < 4; nf++) {
        const int col = nf*8 + tig*2;     // px within tile (even)
        const int oc0 = ocb + g;
        const int oc1 = ocb + g + 8;
        if (MODE == 0) {
            float* o0 = g_up + (((long)(b*CH + oc0))*H + yc)*WID + x0 + col;
            float* o1 = g_up + (((long)(b*CH + oc1))*H + yc)*WID + x0 + col;
            *(float2*)o0 = make_float2(acc[nf][0], acc[nf][1]);
            *(float2*)o1 = make_float2(acc[nf][2], acc[nf][3]);
        } else {
            const int rr = yc + 1;        // 0..256
            float* o0 = g_C2 + (((long)(b*CH + oc0))*C2ROWS + rr)*WID + x0 + col;
            float* o1 = g_C2 + (((long)(b*CH + oc1))*C2ROWS + rr)*WID + x0 + col;
            *(float2*)o0 = make_float2(acc[nf][0], acc[nf][1]);
            *(float2*)o1 = make_float2(acc[nf][2], acc[nf][3]);
        }
    }
}

// ---------------------------------------------------------------------------
// Combine: out = min(upper, w0*C2[y0] + w1*C2[y0+1]).
// Thread = (og of 16 oc, b, y, 4-px group); lanes fastest over x for coalescing.
// ---------------------------------------------------------------------------
__global__ __launch_bounds__(256) void combine_kernel(float* __restrict__ Out) {
    const int NW4 = WID/4;
    int idx = blockIdx.x * 256 + threadIdx.x;
    const int TOT = BATCH * H * NW4 * 4;
    if (idx >= TOT) return;
    int x4 = idx % NW4;  int r2 = idx / NW4;
    int y  = r2 % H;     r2 /= H;
    int b  = r2 % BATCH; int og = r2 / BATCH;
    int x  = x4 * 4;

    int   y0i[4];
    float w0f[4], w1f[4];
    #pragma unroll
    for (int p = 0; p < 4; p++) {
        float s  = g_s[b*HW + y*WID + x + p];
        float ys = (float)y - s;
        float fy = floorf(ys);
        y0i[p] = (int)fy;
        w1f[p] = ys - fy;
        w0f[p] = 1.0f - w1f[p];
    }

    const float* upb = g_up + (long)b*CHW + y*WID + x;
    const float* c2b = g_C2 + (long)b*CH*C2ROWS*WID + x;
    float* ob = Out + (long)b*CHW + y*WID + x;

    #pragma unroll 4
    for (int o = 0; o < 16; o++) {
        int oc = og*16 + o;
        float4 u = *(const float4*)(upb + (long)oc*HW);
        const float* cc = c2b + (long)oc*C2ROWS*WID;
        float r[4];
        #pragma unroll
        for (int p = 0; p < 4; p++) {
            int y0 = y0i[p];
            float A = (y0 >= -1) ? __ldg(cc + (y0+1)*WID + p) : 0.0f;
            float B = (y0 >= -2) ? __ldg(cc + (y0+2)*WID + p) : 0.0f;
            r[p] = w0f[p]*A + w1f[p]*B;
        }
        float4 res = make_float4(fminf(u.x, r[0]), fminf(u.y, r[1]),
                                 fminf(u.z, r[2]), fminf(u.w, r[3]));
        *(float4*)(ob + (long)oc*HW) = res;
    }
}

// ---------------------------------------------------------------------------
extern "C" void kernel_launch(void* const* d_in, const int* in_sizes, int n_in,
                              void* d_out, int out_size) {
    const float* X  = (const float*)d_in[0];   // [4,64,256,256]
    const float* Wg = (const float*)d_in[1];   // [64,64,3,3]
    float* Out = (float*)d_out;                // [4,64,256,256]

    wt_kernel<<<(CH*CH*9 + 255)/256, 256>>>(Wg);
    prep_kernel<<<(BATCH*HW + 255)/256, 256>>>(X);

    // upper = conv3x3(X), rows 0..255
    {
        dim3 grid(WID/NPX, H, BATCH);
        conv_mma_kernel<0><<<grid, 128>>>(X);
    }
    // C2 = conv3x3(x2), center rows -1..255
    {
        float* x2p;  cudaGetSymbolAddress((void**)&x2p, g_x2);
        dim3 grid(WID/NPX, C2ROWS, BATCH);
        conv_mma_kernel<1><<<grid, 128>>>(x2p);
    }
    // interp + min epilogue
    {
        int tot = BATCH * H * (WID/4) * 4;
        combine_kernel<<<(tot + 255)/256, 256>>>(Out);
    }
}

// round 11
// speedup vs baseline: 3.3261x; 1.3085x over previous
#include <cuda_runtime.h>
#include <cuda_bf16.h>
#include <cstdint>

#define BATCH 4
#define CH    64
#define H     256
#define WID   256
#define HW    (H*WID)
#define CHW   (CH*HW)
#define C2ROWS 257          // center rows -1..255 stored at index yc+1
#define NPX   32            // pixels per block (N tile)
#define RS    24            // smem row stride in halves (48B -> conflict-free ldmatrix)

// scratch (allocation-free: __device__ globals)
__device__ float g_s[BATCH*HW];                    // per-pixel vertical shift s
__device__ float g_x2[BATCH*CHW];                  // warped image
__device__ float g_C2[BATCH*CH*C2ROWS*WID];        // conv3x3(x2) at rows -1..255
// weights as per-lane mma A fragments: [cc][tap][warp][lane] -> uint4 (4 regs)
__device__ __align__(16) __nv_bfloat16 g_Wah[4*9*4*32*8];
__device__ __align__(16) __nv_bfloat16 g_Wal[4*9*4*32*8];

// ---------------------------------------------------------------------------
__device__ __forceinline__ void mma16816(float* d, const uint32_t* a, uint32_t b0, uint32_t b1) {
    asm volatile(
        "mma.sync.aligned.m16n8k16.row.col.f32.bf16.bf16.f32 "
        "{%0,%1,%2,%3}, {%4,%5,%6,%7}, {%8,%9}, {%0,%1,%2,%3};\n"
        : "+f"(d[0]), "+f"(d[1]), "+f"(d[2]), "+f"(d[3])
        : "r"(a[0]), "r"(a[1]), "r"(a[2]), "r"(a[3]), "r"(b0), "r"(b1));
}

__device__ __forceinline__ void ldsm4(uint32_t* r, uint32_t addr) {
    asm volatile("ldmatrix.sync.aligned.m8n8.x4.shared.b16 {%0,%1,%2,%3}, [%4];"
        : "=r"(r[0]), "=r"(r[1]), "=r"(r[2]), "=r"(r[3]) : "r"(addr));
}

// ---------------------------------------------------------------------------
// Kernel W: split weights into bf16 hi/lo and scatter into per-lane A-fragment
// layout: dst = ((((cc*9+tap)*4 + w)*32 + lane)*4 + reg)*2 + pair
// ---------------------------------------------------------------------------
__global__ __launch_bounds__(256) void wt_kernel(const float* __restrict__ Wg) {
    int i = blockIdx.x * 256 + threadIdx.x;
    if (i >= CH*CH*9) return;
    int oc  = i / (CH*9);
    int rem = i - oc*CH*9;
    int c   = rem / 9;
    int tap = rem - c*9;
    float wv = Wg[i];
    __nv_bfloat16 h = __float2bfloat16(wv);
    __nv_bfloat16 l = __float2bfloat16(wv - __bfloat162float(h));

    int w    = oc >> 4;
    int ocw  = oc & 15;
    int g    = ocw & 7;
    int hi8  = ocw >> 3;
    int cc   = c >> 4;
    int cp   = c & 15;
    int tig  = (cp >> 1) & 3;
    int khalf= cp >> 3;
    int pair = cp & 1;
    int reg  = hi8 + 2*khalf;
    int lane = g*4 + tig;
    int dst  = ((((cc*9 + tap)*4 + w)*32 + lane)*4 + reg)*2 + pair;
    g_Wah[dst] = h;
    g_Wal[dst] = l;
}

// ---------------------------------------------------------------------------
// Kernel A: per-pixel channel max -> depth -> s, and vertical bilinear warp x2
// ---------------------------------------------------------------------------
__global__ __launch_bounds__(256) void prep_kernel(const float* __restrict__ X) {
    int idx = blockIdx.x * 256 + threadIdx.x;
    if (idx >= BATCH*HW) return;
    int b   = idx / HW;
    int rem = idx - b*HW;
    int y   = rem / WID;
    int x   = rem - y*WID;

    const float* Xpix = X + b*CHW + y*WID + x;
    float m = -1e30f;
    #pragma unroll 8
    for (int c = 0; c < CH; c++) m = fmaxf(m, Xpix[c*HW]);

    float depth = fminf(fmaxf(m, 1.0f), 50.0f);
    float s = 50.0f / (2.0f * depth);
    g_s[idx] = s;

    float ys = (float)y - s;
    float fy = floorf(ys);
    int   y0 = (int)fy;
    float w1 = ys - fy;
    float w0 = 1.0f - w1;

    bool ok0 = (y0   >= 0) && (y0   < H);
    bool ok1 = (y0+1 >= 0) && (y0+1 < H);
    const float* Xc0 = X + b*CHW + (ok0 ? y0   : 0)*WID + x;
    const float* Xc1 = X + b*CHW + (ok1 ? y0+1 : 0)*WID + x;
    float* X2p = g_x2 + b*CHW + y*WID + x;

    #pragma unroll 4
    for (int c = 0; c < CH; c++) {
        float a  = ok0 ? Xc0[c*HW] : 0.0f;
        float bb = ok1 ? Xc1[c*HW] : 0.0f;
        X2p[c*HW] = w0*a + w1*bb;
    }
}

// ---------------------------------------------------------------------------
// Tensor-core conv: block = 64 oc x 32 px for one (b, center-row).
// 128 threads = 4 warps; warp w computes oc rows [16w,16w+16) x all 32 px.
// B fragments via ldmatrix.x4 from 48B-stride padded smem; A fragments via
// LDG.128 of pre-permuted weights. 3-mma bf16 hi/lo split (hh + hl + lh).
// MODE 1: in = g_x2, yc in [-1,255], store C2 at row index yc+1.
// MODE 0: in = X, yc in [0,255], fused epilogue:
//         out = min(conv(X), w0*C2[y0+1] + w1*C2[y0+2]) written to Out.
// ---------------------------------------------------------------------------
template<int MODE>
__global__ __launch_bounds__(128) void conv_mma_kernel(const float* __restrict__ in,
                                                       float* __restrict__ Out) {
    __shared__ __align__(16) __nv_bfloat16 sBh[2][3][34][RS];
    __shared__ __align__(16) __nv_bfloat16 sBl[2][3][34][RS];

    const int t    = threadIdx.x;
    const int w    = t >> 5;
    const int lane = t & 31;
    const int g    = lane >> 2;
    const int tig  = lane & 3;

    const int x0 = blockIdx.x * NPX;
    const int yc = MODE ? ((int)blockIdx.y - 1) : (int)blockIdx.y;
    const int b  = blockIdx.z;

    float acc[4][4];
    #pragma unroll
    for (int nf = 0; nf < 4; nf++)
        #pragma unroll
        for (int k = 0; k < 4; k++) acc[nf][k] = 0.0f;

    // ldmatrix per-thread address component: matrix index = lane/8
    const int rowadd = ((lane >> 4) & 1) * 8 + (lane & 7);   // row within 16-row span
    const int coladd = ((lane >> 3) & 1) * 8;                // channel-half select
    const uint32_t sbH = (uint32_t)__cvta_generic_to_shared(&sBh[0][0][0][0]);
    const uint32_t sbL = (uint32_t)__cvta_generic_to_shared(&sBl[0][0][0][0]);
    const uint32_t BUFB = 3*34*RS*2;                          // bytes per buffer
    const uint32_t tb  = (uint32_t)(rowadd*RS + coladd) * 2;  // per-thread byte offset

    // ---- stage one 16-channel chunk of 3 input rows (hi/lo bf16, paired STS) ----
    auto stage = [&](int buf, int cc) {
        const float* inb = in + ((long)b*CH + cc*16)*HW;
        for (int i = t; i < 8*3*34; i += 128) {
            int cpp = i / 102;
            int rem = i - cpp*102;
            int r   = rem / 34;
            int px  = rem - r*34;
            int cp  = cpp*2;
            int row = yc + r - 1;
            int col = x0 + px - 1;
            float v0 = 0.0f, v1 = 0.0f;
            if (row >= 0 && row < H && col >= 0 && col < WID) {
                const float* p = inb + (long)cp*HW + row*WID + col;
                v0 = __ldg(p);
                v1 = __ldg(p + HW);
            }
            __nv_bfloat16 h0 = __float2bfloat16(v0);
            __nv_bfloat16 h1 = __float2bfloat16(v1);
            __nv_bfloat16 l0 = __float2bfloat16(v0 - __bfloat162float(h0));
            __nv_bfloat16 l1 = __float2bfloat16(v1 - __bfloat162float(h1));
            *(__nv_bfloat162*)&sBh[buf][r][px][cp] = __nv_bfloat162(h0, h1);
            *(__nv_bfloat162*)&sBl[buf][r][px][cp] = __nv_bfloat162(l0, l1);
        }
    };

    stage(0, 0);
    __syncthreads();
    int buf = 0;

    const uint4* WAh = (const uint4*)g_Wah;
    const uint4* WAl = (const uint4*)g_Wal;

    for (int cc = 0; cc < 4; cc++) {
        if (cc < 3) stage(buf ^ 1, cc + 1);

        #pragma unroll
        for (int tap = 0; tap < 9; tap++) {
            const int ky = tap / 3;
            const int kx = tap - ky*3;

            const int aidx = ((cc*9 + tap)*4 + w)*32 + lane;
            uint4 a4h = __ldg(WAh + aidx);
            uint4 a4l = __ldg(WAl + aidx);
            uint32_t ah[4] = {a4h.x, a4h.y, a4h.z, a4h.w};
            uint32_t al[4] = {a4l.x, a4l.y, a4l.z, a4l.w};

            #pragma unroll
            for (int P = 0; P < 2; P++) {
                const uint32_t off = (uint32_t)buf*BUFB + tb
                                   + (uint32_t)((ky*34 + kx + P*16)*RS)*2;
                uint32_t bh[4], bl[4];
                ldsm4(bh, sbH + off);
                ldsm4(bl, sbL + off);
                const int nf0 = P*2, nf1 = P*2 + 1;
                mma16816(acc[nf0], ah, bh[0], bh[1]);
                mma16816(acc[nf0], ah, bl[0], bl[1]);
                mma16816(acc[nf0], al, bh[0], bh[1]);
                mma16816(acc[nf1], ah, bh[2], bh[3]);
                mma16816(acc[nf1], ah, bl[2], bl[3]);
                mma16816(acc[nf1], al, bh[2], bh[3]);
            }
        }
        __syncthreads();
        buf ^= 1;
    }

    // ---- epilogue ----
    const int ocb = w*16;
    if (MODE == 1) {
        const int rr = yc + 1;            // 0..256
        #pragma unroll
        for (int nf = 0; nf < 4; nf++) {
            const int col = nf*8 + tig*2;
            float* o0 = g_C2 + (((long)(b*CH + ocb + g    ))*C2ROWS + rr)*WID + x0 + col;
            float* o1 = g_C2 + (((long)(b*CH + ocb + g + 8))*C2ROWS + rr)*WID + x0 + col;
            *(float2*)o0 = make_float2(acc[nf][0], acc[nf][1]);
            *(float2*)o1 = make_float2(acc[nf][2], acc[nf][3]);
        }
    } else {
        #pragma unroll
        for (int nf = 0; nf < 4; nf++) {
            const int col = nf*8 + tig*2;
            const int x = x0 + col;
            float2 sv = *(const float2*)&g_s[b*HW + yc*WID + x];

            float ysA = (float)yc - sv.x;
            float fA  = floorf(ysA);
            int   yA  = (int)fA;
            float w1A = ysA - fA, w0A = 1.0f - w1A;

            float ysB = (float)yc - sv.y;
            float fB  = floorf(ysB);
            int   yB  = (int)fB;
            float w1B = ysB - fB, w0B = 1.0f - w1B;

            const int oc0 = ocb + g, oc1 = ocb + g + 8;
            const float* c0 = g_C2 + ((long)(b*CH + oc0))*C2ROWS*WID + x;
            const float* c1 = g_C2 + ((long)(b*CH + oc1))*C2ROWS*WID + x;

            float A0 = (yA >= -1) ? __ldg(c0 + (yA+1)*WID)     : 0.0f;
            float A1 = (yA >= -2) ? __ldg(c0 + (yA+2)*WID)     : 0.0f;
            float B0 = (yB >= -1) ? __ldg(c0 + (yB+1)*WID + 1) : 0.0f;
            float B1 = (yB >= -2) ? __ldg(c0 + (yB+2)*WID + 1) : 0.0f;
            float r00 = fminf(acc[nf][0], w0A*A0 + w1A*A1);
            float r01 = fminf(acc[nf][1], w0B*B0 + w1B*B1);

            float C0 = (yA >= -1) ? __ldg(c1 + (yA+1)*WID)     : 0.0f;
            float C1 = (yA >= -2) ? __ldg(c1 + (yA+2)*WID)     : 0.0f;
            float D0 = (yB >= -1) ? __ldg(c1 + (yB+1)*WID + 1) : 0.0f;
            float D1 = (yB >= -2) ? __ldg(c1 + (yB+2)*WID + 1) : 0.0f;
            float r10 = fminf(acc[nf][2], w0A*C0 + w1A*C1);
            float r11 = fminf(acc[nf][3], w0B*D0 + w1B*D1);

            float* o0 = Out + ((long)(b*CH + oc0))*HW + yc*WID + x;
            float* o1 = Out + ((long)(b*CH + oc1))*HW + yc*WID + x;
            *(float2*)o0 = make_float2(r00, r01);
            *(float2*)o1 = make_float2(r10, r11);
        }
    }
}

// ---------------------------------------------------------------------------
extern "C" void kernel_launch(void* const* d_in, const int* in_sizes, int n_in,
                              void* d_out, int out_size) {
    const float* X  = (const float*)d_in[0];   // [4,64,256,256]
    const float* Wg = (const float*)d_in[1];   // [64,64,3,3]
    float* Out = (float*)d_out;                // [4,64,256,256]

    wt_kernel<<<(CH*CH*9 + 255)/256, 256>>>(Wg);
    prep_kernel<<<(BATCH*HW + 255)/256, 256>>>(X);

    // C2 = conv3x3(x2), center rows -1..255
    {
        float* x2p;  cudaGetSymbolAddress((void**)&x2p, g_x2);
        dim3 grid(WID/NPX, C2ROWS, BATCH);
        conv_mma_kernel<1><<<grid, 128>>>(x2p, nullptr);
    }
    // upper conv on X with fused interp/min epilogue -> Out
    {
        dim3 grid(WID/NPX, H, BATCH);
        conv_mma_kernel<0><<<grid, 128>>>(X, Out);
    }
}